// round 5
// baseline (speedup 1.0000x reference)
#include <cuda_runtime.h>
#include <cuda_bf16.h>

// ---------------- scratch (device globals; no allocs allowed) ----------------
__device__ __align__(16) float g_T1[4 * 132 * 64];   // conv1 tap table [tap][combo][oc]
__device__ __align__(16) float g_GI[100 * 384];      // GRU input proj table [word][gate]
__device__ __align__(16) float g_ht[8192 * 128];     // GRU final hidden
__device__ __align__(16) float g_x[8192 * 128];      // conv output (LSTM input)
// transposed weights: dst[(k>>2)*N*4 + row*4 + (k&3)]  (k,k+1 adjacent -> f32x2-packable)
__device__ __align__(16) float g_wihT[512 * 128];
__device__ __align__(16) float g_whhT[512 * 128];
__device__ __align__(16) float g_gwhhT[384 * 128];
__device__ __align__(16) float g_aw1T[256 * 256];
__device__ __align__(16) float g_cw1T[256 * 256];
__device__ __align__(16) float g_w2T[64 * 256];
__device__ __align__(16) float g_w3T[128 * 256];

__device__ __forceinline__ float sigm_(float x) { return 1.0f / (1.0f + __expf(-x)); }
__device__ __forceinline__ float tanh_(float x) { return 2.0f / (1.0f + __expf(-2.0f * x)) - 1.0f; }

// packed fp32x2 FMA: acc.{lo,hi} += a.{lo,hi} * b.{lo,hi}
__device__ __forceinline__ void fma2(unsigned long long& acc,
                                     unsigned long long a, unsigned long long b) {
    asm("fma.rn.f32x2 %0, %1, %2, %0;" : "+l"(acc) : "l"(a), "l"(b));
}
__device__ __forceinline__ float hsum2(unsigned long long a) {
    return __uint_as_float((unsigned)(a & 0xffffffffull)) +
           __uint_as_float((unsigned)(a >> 32));
}
__device__ __forceinline__ unsigned long long init2(float bias) {
    return (unsigned long long)__float_as_uint(bias);   // lo=bias, hi=0
}

// ---------------- K0: fused transpose prep (one launch) ----------------------
__global__ void k_prep(const float* __restrict__ lwih, const float* __restrict__ lwhh,
                       const float* __restrict__ gwhh, const float* __restrict__ aw1,
                       const float* __restrict__ cw1, const float* __restrict__ c2w,
                       const float* __restrict__ c3w) {
    int m = blockIdx.y;
    const float* src; float* dst; int N, K;
    switch (m) {
        case 0: src = lwih; dst = g_wihT;  N = 512; K = 128; break;
        case 1: src = lwhh; dst = g_whhT;  N = 512; K = 128; break;
        case 2: src = gwhh; dst = g_gwhhT; N = 384; K = 128; break;
        case 3: src = aw1;  dst = g_aw1T;  N = 256; K = 256; break;
        case 4: src = cw1;  dst = g_cw1T;  N = 256; K = 256; break;
        case 5: src = c2w;  dst = g_w2T;   N = 64;  K = 256; break;
        default:src = c3w;  dst = g_w3T;   N = 128; K = 256; break;
    }
    int total = N * K;
    for (int idx = blockIdx.x * blockDim.x + threadIdx.x; idx < total;
         idx += gridDim.x * blockDim.x) {
        int j = idx / K, k = idx % K;
        dst[(k >> 2) * (N * 4) + j * 4 + (k & 3)] = src[idx];
    }
}

// ---------------- K1: conv1 tap table ----------------
__global__ void k_build_t1(const float* __restrict__ obj_emb,
                           const float* __restrict__ col_emb,
                           const float* __restrict__ st_emb,
                           const float* __restrict__ w1) {
    int blk = blockIdx.x;            // tap*132 + combo
    int tap = blk / 132, combo = blk % 132;
    int ty = tap >> 1, tx = tap & 1;
    int s = combo & 1;
    int q = combo >> 1;
    int cc = q % 6, o = q / 6;
    __shared__ __align__(16) float ev[48];
    int t = threadIdx.x;             // 64
    if (t < 16)       ev[t] = col_emb[cc * 16 + t];
    else if (t < 32)  ev[t] = obj_emb[o * 16 + (t - 16)];
    else if (t < 48)  ev[t] = st_emb[s * 16 + (t - 32)];
    __syncthreads();
    float v = 0.f;
    #pragma unroll 8
    for (int k = 0; k < 48; k++)
        v += w1[((t * 48 + k) * 2 + ty) * 2 + tx] * ev[k];
    g_T1[(tap * 132 + combo) * 64 + t] = v;
}

// ---------------- K2: GRU input-projection table ----------------
__global__ void k_build_gi(const float* __restrict__ word_emb,
                           const float* __restrict__ gwih,
                           const float* __restrict__ gbih) {
    int v = blockIdx.x;              // 100
    int g = threadIdx.x;             // 384
    __shared__ __align__(16) float ev[32];
    if (g < 32) ev[g] = word_emb[v * 32 + g];
    __syncthreads();
    float a = gbih[g];
    const float* w = gwih + g * 32;
    #pragma unroll 8
    for (int k = 0; k < 32; k++) a += w[k] * ev[k];
    g_GI[v * 384 + g] = a;
}

// ---------------- K3: conv stack (2 elems / block, 256 threads) ---------------
__global__ __launch_bounds__(256)
void k_conv(const int* __restrict__ image,
            const float* __restrict__ b1, const float* __restrict__ b2,
            const float* __restrict__ b3) {
    int t = threadIdx.x;
    int half = t >> 7, st = t & 127;
    int b = blockIdx.x * 2 + half;
    __shared__ __align__(16) int   s_combo[2][49];
    __shared__ __align__(16) float s_c1[2][36 * 64];   // [pos][c]
    __shared__ __align__(16) float s_p[2][9 * 64];
    __shared__ __align__(16) float s_q[2][4 * 64];

    if (t < 98) {
        int h2 = t / 49, li = t % 49;
        int bb = blockIdx.x * 2 + h2;
        const int* px = image + (bb * 49 + li) * 3;
        s_combo[h2][li] = (px[0] * 6 + px[1]) * 2 + px[2];
    }
    __syncthreads();

    // conv1 via tap table + relu; lanes over channel c
    for (int idx = st; idx < 36 * 64; idx += 128) {
        int c = idx & 63, pos = idx >> 6;
        int y = pos / 6, x = pos % 6;
        float v = b1[c];
        v += g_T1[(0 * 132 + s_combo[half][y * 7 + x]) * 64 + c];
        v += g_T1[(1 * 132 + s_combo[half][y * 7 + x + 1]) * 64 + c];
        v += g_T1[(2 * 132 + s_combo[half][(y + 1) * 7 + x]) * 64 + c];
        v += g_T1[(3 * 132 + s_combo[half][(y + 1) * 7 + x + 1]) * 64 + c];
        s_c1[half][pos * 64 + c] = fmaxf(v, 0.f);
    }
    __syncthreads();

    // maxpool 2x2 stride 2 -> (3,3,64)
    for (int idx = st; idx < 9 * 64; idx += 128) {
        int c = idx & 63, pos = idx >> 6;
        int y = pos / 3, x = pos % 3;
        int p0 = (2 * y) * 6 + 2 * x;
        float v = fmaxf(fmaxf(s_c1[half][p0 * 64 + c], s_c1[half][(p0 + 1) * 64 + c]),
                        fmaxf(s_c1[half][(p0 + 6) * 64 + c], s_c1[half][(p0 + 7) * 64 + c]));
        s_p[half][pos * 64 + c] = v;
    }
    __syncthreads();

    // conv2 2x2 -> (2,2,64) + relu
    for (int idx = st; idx < 256; idx += 128) {
        int c = idx & 63, pos = idx >> 6;
        int y = pos >> 1, x = pos & 1;
        float v = b2[c];
        int p00 = y * 3 + x;
        #pragma unroll 8
        for (int ci = 0; ci < 64; ci++) {
            float4 w4 = *(const float4*)(g_w2T + ci * 256 + c * 4);
            v += w4.x * s_p[half][p00 * 64 + ci] + w4.y * s_p[half][(p00 + 1) * 64 + ci]
               + w4.z * s_p[half][(p00 + 3) * 64 + ci] + w4.w * s_p[half][(p00 + 4) * 64 + ci];
        }
        s_q[half][pos * 64 + c] = fmaxf(v, 0.f);
    }
    __syncthreads();

    // conv3 2x2 -> (128,) + relu; thread st = output channel
    {
        float v = b3[st];
        #pragma unroll 8
        for (int ci = 0; ci < 64; ci++) {
            float4 w4 = *(const float4*)(g_w3T + ci * 512 + st * 4);
            v += w4.x * s_q[half][0 * 64 + ci] + w4.y * s_q[half][1 * 64 + ci]
               + w4.z * s_q[half][2 * 64 + ci] + w4.w * s_q[half][3 * 64 + ci];
        }
        g_x[b * 128 + st] = fmaxf(v, 0.f);
    }
}

// ---------------- K4: LSTM (8 elems/block, 128 threads, f32x2-packed) ---------
__global__ __launch_bounds__(128)
void k_lstm(const float* __restrict__ memory,
            const float* __restrict__ bih, const float* __restrict__ bhh,
            float* __restrict__ mem_out) {
    int j = threadIdx.x;
    int b0 = blockIdx.x * 8;
    __shared__ __align__(16) float s_x[8 * 128];
    __shared__ __align__(16) float s_h[8 * 128];
    for (int idx = j; idx < 8 * 128; idx += 128) {
        int bi = idx >> 7, k = idx & 127;
        s_x[idx] = g_x[(b0 + bi) * 128 + k];
        s_h[idx] = memory[(b0 + bi) * 256 + k];
    }
    unsigned long long a0[8], a1[8], a2[8], a3[8];
    float bb0 = bih[j]       + bhh[j];
    float bb1 = bih[128 + j] + bhh[128 + j];
    float bb2 = bih[256 + j] + bhh[256 + j];
    float bb3 = bih[384 + j] + bhh[384 + j];
    #pragma unroll
    for (int bi = 0; bi < 8; bi++) {
        a0[bi] = init2(bb0); a1[bi] = init2(bb1);
        a2[bi] = init2(bb2); a3[bi] = init2(bb3);
    }
    __syncthreads();

    for (int kc = 0; kc < 32; kc++) {
        {   // input-to-hidden
            ulonglong2 w0 = *(const ulonglong2*)(g_wihT + kc * 2048 + j * 4);
            ulonglong2 w1 = *(const ulonglong2*)(g_wihT + kc * 2048 + (128 + j) * 4);
            ulonglong2 w2 = *(const ulonglong2*)(g_wihT + kc * 2048 + (256 + j) * 4);
            ulonglong2 w3 = *(const ulonglong2*)(g_wihT + kc * 2048 + (384 + j) * 4);
            #pragma unroll
            for (int bi = 0; bi < 8; bi++) {
                ulonglong2 xv = *(const ulonglong2*)(s_x + bi * 128 + kc * 4);
                fma2(a0[bi], w0.x, xv.x); fma2(a0[bi], w0.y, xv.y);
                fma2(a1[bi], w1.x, xv.x); fma2(a1[bi], w1.y, xv.y);
                fma2(a2[bi], w2.x, xv.x); fma2(a2[bi], w2.y, xv.y);
                fma2(a3[bi], w3.x, xv.x); fma2(a3[bi], w3.y, xv.y);
            }
        }
        {   // hidden-to-hidden
            ulonglong2 w0 = *(const ulonglong2*)(g_whhT + kc * 2048 + j * 4);
            ulonglong2 w1 = *(const ulonglong2*)(g_whhT + kc * 2048 + (128 + j) * 4);
            ulonglong2 w2 = *(const ulonglong2*)(g_whhT + kc * 2048 + (256 + j) * 4);
            ulonglong2 w3 = *(const ulonglong2*)(g_whhT + kc * 2048 + (384 + j) * 4);
            #pragma unroll
            for (int bi = 0; bi < 8; bi++) {
                ulonglong2 hv = *(const ulonglong2*)(s_h + bi * 128 + kc * 4);
                fma2(a0[bi], w0.x, hv.x); fma2(a0[bi], w0.y, hv.y);
                fma2(a1[bi], w1.x, hv.x); fma2(a1[bi], w1.y, hv.y);
                fma2(a2[bi], w2.x, hv.x); fma2(a2[bi], w2.y, hv.y);
                fma2(a3[bi], w3.x, hv.x); fma2(a3[bi], w3.y, hv.y);
            }
        }
    }
    #pragma unroll
    for (int bi = 0; bi < 8; bi++) {
        float c_in = memory[(b0 + bi) * 256 + 128 + j];
        float cn = sigm_(hsum2(a1[bi])) * c_in + sigm_(hsum2(a0[bi])) * tanh_(hsum2(a2[bi]));
        float hn = sigm_(hsum2(a3[bi])) * tanh_(cn);
        mem_out[(b0 + bi) * 256 + j] = hn;
        mem_out[(b0 + bi) * 256 + 128 + j] = cn;
    }
}

// ---------------- K5: GRU over 20 steps (8 batch / block, f32x2-packed) -------
__global__ __launch_bounds__(128)
void k_gru(const int* __restrict__ text, const float* __restrict__ bhh) {
    int j = threadIdx.x;
    int b0 = blockIdx.x * 8;
    __shared__ __align__(16) float s_ht[8 * 128];
    __shared__ __align__(16) int s_w[8 * 20];
    for (int idx = j; idx < 160; idx += 128) s_w[idx] = text[b0 * 20 + idx];
    #pragma unroll
    for (int bi = 0; bi < 8; bi++) s_ht[bi * 128 + j] = 0.f;
    float htj[8];
    #pragma unroll
    for (int bi = 0; bi < 8; bi++) htj[bi] = 0.f;
    float bh_r = bhh[j], bh_z = bhh[128 + j], bh_n = bhh[256 + j];
    __syncthreads();

    for (int tt = 0; tt < 20; tt++) {
        unsigned long long ar[8], az[8], an[8];
        #pragma unroll
        for (int bi = 0; bi < 8; bi++) {
            ar[bi] = init2(bh_r); az[bi] = init2(bh_z); an[bi] = init2(bh_n);
        }
        for (int kc = 0; kc < 32; kc++) {
            ulonglong2 wr = *(const ulonglong2*)(g_gwhhT + kc * 1536 + j * 4);
            ulonglong2 wz = *(const ulonglong2*)(g_gwhhT + kc * 1536 + (128 + j) * 4);
            ulonglong2 wn = *(const ulonglong2*)(g_gwhhT + kc * 1536 + (256 + j) * 4);
            #pragma unroll
            for (int bi = 0; bi < 8; bi++) {
                ulonglong2 hv = *(const ulonglong2*)(s_ht + bi * 128 + kc * 4);
                fma2(ar[bi], wr.x, hv.x); fma2(ar[bi], wr.y, hv.y);
                fma2(az[bi], wz.x, hv.x); fma2(az[bi], wz.y, hv.y);
                fma2(an[bi], wn.x, hv.x); fma2(an[bi], wn.y, hv.y);
            }
        }
        __syncthreads();
        #pragma unroll
        for (int bi = 0; bi < 8; bi++) {
            const float* gi = g_GI + s_w[bi * 20 + tt] * 384;
            float r = sigm_(gi[j] + hsum2(ar[bi]));
            float z = sigm_(gi[128 + j] + hsum2(az[bi]));
            float n = tanh_(gi[256 + j] + r * hsum2(an[bi]));
            float h = (1.f - z) * n + z * htj[bi];
            htj[bi] = h;
            s_ht[bi * 128 + j] = h;
        }
        __syncthreads();
    }
    #pragma unroll
    for (int bi = 0; bi < 8; bi++) g_ht[(b0 + bi) * 128 + j] = htj[bi];
}

// ---------------- K6: actor/critic heads (16 batch / block, 256 threads) -----
__global__ __launch_bounds__(256)
void k_heads(const float* __restrict__ mem,
             const float* __restrict__ ab1, const float* __restrict__ aw2,
             const float* __restrict__ ab2, const float* __restrict__ cb1,
             const float* __restrict__ cw2, const float* __restrict__ cb2,
             float* __restrict__ lp, float* __restrict__ value) {
    int tid = threadIdx.x;
    int b0 = blockIdx.x * 16;
    __shared__ __align__(16) float s_emb[16 * 256];
    __shared__ __align__(16) float s_a1[16 * 256];
    __shared__ __align__(16) float s_logits[16 * 8];

    for (int idx = tid; idx < 16 * 128; idx += 256) {
        int bi = idx >> 7, k = idx & 127;
        s_emb[bi * 256 + k]       = mem[(b0 + bi) * 256 + k];
        s_emb[bi * 256 + 128 + k] = g_ht[(b0 + bi) * 128 + k];
    }
    __syncthreads();

    // actor layer 1 (packed)
    {
        unsigned long long acc[16];
        float bb = ab1[tid];
        #pragma unroll
        for (int bi = 0; bi < 16; bi++) acc[bi] = init2(bb);
        for (int kc = 0; kc < 64; kc++) {
            ulonglong2 w = *(const ulonglong2*)(g_aw1T + kc * 1024 + tid * 4);
            #pragma unroll
            for (int bi = 0; bi < 16; bi++) {
                ulonglong2 e = *(const ulonglong2*)(s_emb + bi * 256 + kc * 4);
                fma2(acc[bi], w.x, e.x); fma2(acc[bi], w.y, e.y);
            }
        }
        #pragma unroll
        for (int bi = 0; bi < 16; bi++) s_a1[bi * 256 + tid] = tanh_(hsum2(acc[bi]));
    }
    __syncthreads();

    int warp = tid >> 5, lane = tid & 31;
    for (int bi = warp * 2; bi < warp * 2 + 2; bi++) {
        for (int a = 0; a < 7; a++) {
            float s = 0.f;
            for (int k = lane; k < 256; k += 32) s += aw2[a * 256 + k] * s_a1[bi * 256 + k];
            #pragma unroll
            for (int off = 16; off; off >>= 1) s += __shfl_xor_sync(0xffffffffu, s, off);
            if (lane == 0) s_logits[bi * 8 + a] = s + ab2[a];
        }
    }
    __syncthreads();

    // critic layer 1 (packed; reuses s_a1)
    {
        unsigned long long acc[16];
        float bb = cb1[tid];
        #pragma unroll
        for (int bi = 0; bi < 16; bi++) acc[bi] = init2(bb);
        for (int kc = 0; kc < 64; kc++) {
            ulonglong2 w = *(const ulonglong2*)(g_cw1T + kc * 1024 + tid * 4);
            #pragma unroll
            for (int bi = 0; bi < 16; bi++) {
                ulonglong2 e = *(const ulonglong2*)(s_emb + bi * 256 + kc * 4);
                fma2(acc[bi], w.x, e.x); fma2(acc[bi], w.y, e.y);
            }
        }
        #pragma unroll
        for (int bi = 0; bi < 16; bi++) s_a1[bi * 256 + tid] = tanh_(hsum2(acc[bi]));
    }
    if (tid < 16) {
        float m = -1e30f;
        #pragma unroll
        for (int a = 0; a < 7; a++) m = fmaxf(m, s_logits[tid * 8 + a]);
        float sum = 0.f;
        #pragma unroll
        for (int a = 0; a < 7; a++) sum += expf(s_logits[tid * 8 + a] - m);
        float lse = m + logf(sum);
        #pragma unroll
        for (int a = 0; a < 7; a++) lp[(b0 + tid) * 7 + a] = s_logits[tid * 8 + a] - lse;
    }
    __syncthreads();

    for (int bi = warp * 2; bi < warp * 2 + 2; bi++) {
        float s = 0.f;
        for (int k = lane; k < 256; k += 32) s += cw2[k] * s_a1[bi * 256 + k];
        #pragma unroll
        for (int off = 16; off; off >>= 1) s += __shfl_xor_sync(0xffffffffu, s, off);
        if (lane == 0) value[b0 + bi] = s + cb2[0];
    }
}

// ---------------- launch ----------------
extern "C" void kernel_launch(void* const* d_in, const int* in_sizes, int n_in,
                              void* d_out, int out_size) {
    const int*   image  = (const int*)  d_in[0];
    const float* memory = (const float*)d_in[1];
    const int*   text   = (const int*)  d_in[2];
    const float* obj_e  = (const float*)d_in[3];
    const float* col_e  = (const float*)d_in[4];
    const float* st_e   = (const float*)d_in[5];
    const float* c1w    = (const float*)d_in[6];
    const float* c1b    = (const float*)d_in[7];
    const float* c2w    = (const float*)d_in[8];
    const float* c2b    = (const float*)d_in[9];
    const float* c3w    = (const float*)d_in[10];
    const float* c3b    = (const float*)d_in[11];
    const float* lwih   = (const float*)d_in[12];
    const float* lwhh   = (const float*)d_in[13];
    const float* lbih   = (const float*)d_in[14];
    const float* lbhh   = (const float*)d_in[15];
    const float* wemb   = (const float*)d_in[16];
    const float* gwih   = (const float*)d_in[17];
    const float* gwhh   = (const float*)d_in[18];
    const float* gbih   = (const float*)d_in[19];
    const float* gbhh   = (const float*)d_in[20];
    const float* aw1    = (const float*)d_in[21];
    const float* ab1    = (const float*)d_in[22];
    const float* aw2    = (const float*)d_in[23];
    const float* ab2    = (const float*)d_in[24];
    const float* cw1    = (const float*)d_in[25];
    const float* cb1    = (const float*)d_in[26];
    const float* cw2    = (const float*)d_in[27];
    const float* cb2    = (const float*)d_in[28];

    const int B = in_sizes[1] / 256;   // 8192
    float* out   = (float*)d_out;
    float* lp    = out;                 // (B,7)
    float* value = out + (size_t)B * 7; // (B,)
    float* memo  = out + (size_t)B * 8; // (B,256)

    dim3 pgrid(64, 7);
    k_prep<<<pgrid, 256>>>(lwih, lwhh, gwhh, aw1, cw1, c2w, c3w);
    k_build_t1<<<4 * 132, 64>>>(obj_e, col_e, st_e, c1w);
    k_build_gi<<<100, 384>>>(wemb, gwih, gbih);

    k_conv<<<B / 2, 256>>>(image, c1b, c2b, c3b);
    k_lstm<<<B / 8, 128>>>(memory, lbih, lbhh, memo);
    k_gru<<<B / 8, 128>>>(text, gbhh);
    k_heads<<<B / 16, 256>>>(memo, ab1, aw2, ab2, cb1, cw2, cb2, lp, value);
}

// round 6
// speedup vs baseline: 1.0019x; 1.0019x over previous
#include <cuda_runtime.h>
#include <cuda_bf16.h>

// ---------------- scratch (device globals; no allocs allowed) ----------------
__device__ __align__(16) float g_T1[4 * 132 * 64];   // conv1 tap table [tap][combo][oc]
__device__ __align__(16) float g_GI[100 * 384];      // GRU input proj table [word][gate]
__device__ __align__(16) float g_ht[8192 * 128];     // GRU final hidden
__device__ __align__(16) float g_x[8192 * 128];      // conv output (LSTM input)
// transposed weights: dst[(k>>2)*N*4 + row*4 + (k&3)]  (k,k+1 adjacent -> f32x2-packable)
__device__ __align__(16) float g_wihT[512 * 128];
__device__ __align__(16) float g_whhT[512 * 128];
__device__ __align__(16) float g_gwhhT[384 * 128];
__device__ __align__(16) float g_aw1T[256 * 256];
__device__ __align__(16) float g_cw1T[256 * 256];
__device__ __align__(16) float g_w2T[64 * 256];
__device__ __align__(16) float g_w3T[128 * 256];

__device__ __forceinline__ float sigm_(float x) { return 1.0f / (1.0f + __expf(-x)); }
__device__ __forceinline__ float tanh_(float x) { return 2.0f / (1.0f + __expf(-2.0f * x)) - 1.0f; }

// packed fp32x2 FMA: acc.{lo,hi} += a.{lo,hi} * b.{lo,hi}
__device__ __forceinline__ void fma2(unsigned long long& acc,
                                     unsigned long long a, unsigned long long b) {
    asm("fma.rn.f32x2 %0, %1, %2, %0;" : "+l"(acc) : "l"(a), "l"(b));
}
__device__ __forceinline__ float hsum2(unsigned long long a) {
    return __uint_as_float((unsigned)(a & 0xffffffffull)) +
           __uint_as_float((unsigned)(a >> 32));
}
__device__ __forceinline__ unsigned long long init2(float bias) {
    return (unsigned long long)__float_as_uint(bias);   // lo=bias, hi=0
}

// ---------------- K0: fused transpose prep (one launch) ----------------------
__global__ void k_prep(const float* __restrict__ lwih, const float* __restrict__ lwhh,
                       const float* __restrict__ gwhh, const float* __restrict__ aw1,
                       const float* __restrict__ cw1, const float* __restrict__ c2w,
                       const float* __restrict__ c3w) {
    int m = blockIdx.y;
    const float* src; float* dst; int N, K;
    switch (m) {
        case 0: src = lwih; dst = g_wihT;  N = 512; K = 128; break;
        case 1: src = lwhh; dst = g_whhT;  N = 512; K = 128; break;
        case 2: src = gwhh; dst = g_gwhhT; N = 384; K = 128; break;
        case 3: src = aw1;  dst = g_aw1T;  N = 256; K = 256; break;
        case 4: src = cw1;  dst = g_cw1T;  N = 256; K = 256; break;
        case 5: src = c2w;  dst = g_w2T;   N = 64;  K = 256; break;
        default:src = c3w;  dst = g_w3T;   N = 128; K = 256; break;
    }
    int total = N * K;
    for (int idx = blockIdx.x * blockDim.x + threadIdx.x; idx < total;
         idx += gridDim.x * blockDim.x) {
        int j = idx / K, k = idx % K;
        dst[(k >> 2) * (N * 4) + j * 4 + (k & 3)] = src[idx];
    }
}

// ---------------- K1: conv1 tap table ----------------
__global__ void k_build_t1(const float* __restrict__ obj_emb,
                           const float* __restrict__ col_emb,
                           const float* __restrict__ st_emb,
                           const float* __restrict__ w1) {
    int blk = blockIdx.x;            // tap*132 + combo
    int tap = blk / 132, combo = blk % 132;
    int ty = tap >> 1, tx = tap & 1;
    int s = combo & 1;
    int q = combo >> 1;
    int cc = q % 6, o = q / 6;
    __shared__ __align__(16) float ev[48];
    int t = threadIdx.x;             // 64
    if (t < 16)       ev[t] = col_emb[cc * 16 + t];
    else if (t < 32)  ev[t] = obj_emb[o * 16 + (t - 16)];
    else if (t < 48)  ev[t] = st_emb[s * 16 + (t - 32)];
    __syncthreads();
    float v = 0.f;
    #pragma unroll 8
    for (int k = 0; k < 48; k++)
        v += w1[((t * 48 + k) * 2 + ty) * 2 + tx] * ev[k];
    g_T1[(tap * 132 + combo) * 64 + t] = v;
}

// ---------------- K2: GRU input-projection table ----------------
__global__ void k_build_gi(const float* __restrict__ word_emb,
                           const float* __restrict__ gwih,
                           const float* __restrict__ gbih) {
    int v = blockIdx.x;              // 100
    int g = threadIdx.x;             // 384
    __shared__ __align__(16) float ev[32];
    if (g < 32) ev[g] = word_emb[v * 32 + g];
    __syncthreads();
    float a = gbih[g];
    const float* w = gwih + g * 32;
    #pragma unroll 8
    for (int k = 0; k < 32; k++) a += w[k] * ev[k];
    g_GI[v * 384 + g] = a;
}

// ---------------- K3: conv stack (2 elems / block, 256 threads) ---------------
__global__ __launch_bounds__(256)
void k_conv(const int* __restrict__ image,
            const float* __restrict__ b1, const float* __restrict__ b2,
            const float* __restrict__ b3) {
    int t = threadIdx.x;
    int half = t >> 7, st = t & 127;
    int b = blockIdx.x * 2 + half;
    __shared__ __align__(16) int   s_combo[2][49];
    __shared__ __align__(16) float s_c1[2][36 * 64];   // [pos][c]
    __shared__ __align__(16) float s_p[2][9 * 64];
    __shared__ __align__(16) float s_q[2][4 * 64];

    if (t < 98) {
        int h2 = t / 49, li = t % 49;
        int bb = blockIdx.x * 2 + h2;
        const int* px = image + (bb * 49 + li) * 3;
        s_combo[h2][li] = (px[0] * 6 + px[1]) * 2 + px[2];
    }
    __syncthreads();

    // conv1 via tap table + relu; lanes over channel c
    for (int idx = st; idx < 36 * 64; idx += 128) {
        int c = idx & 63, pos = idx >> 6;
        int y = pos / 6, x = pos % 6;
        float v = b1[c];
        v += g_T1[(0 * 132 + s_combo[half][y * 7 + x]) * 64 + c];
        v += g_T1[(1 * 132 + s_combo[half][y * 7 + x + 1]) * 64 + c];
        v += g_T1[(2 * 132 + s_combo[half][(y + 1) * 7 + x]) * 64 + c];
        v += g_T1[(3 * 132 + s_combo[half][(y + 1) * 7 + x + 1]) * 64 + c];
        s_c1[half][pos * 64 + c] = fmaxf(v, 0.f);
    }
    __syncthreads();

    // maxpool 2x2 stride 2 -> (3,3,64)
    for (int idx = st; idx < 9 * 64; idx += 128) {
        int c = idx & 63, pos = idx >> 6;
        int y = pos / 3, x = pos % 3;
        int p0 = (2 * y) * 6 + 2 * x;
        float v = fmaxf(fmaxf(s_c1[half][p0 * 64 + c], s_c1[half][(p0 + 1) * 64 + c]),
                        fmaxf(s_c1[half][(p0 + 6) * 64 + c], s_c1[half][(p0 + 7) * 64 + c]));
        s_p[half][pos * 64 + c] = v;
    }
    __syncthreads();

    // conv2 2x2 -> (2,2,64) + relu
    for (int idx = st; idx < 256; idx += 128) {
        int c = idx & 63, pos = idx >> 6;
        int y = pos >> 1, x = pos & 1;
        float v = b2[c];
        int p00 = y * 3 + x;
        #pragma unroll 8
        for (int ci = 0; ci < 64; ci++) {
            float4 w4 = *(const float4*)(g_w2T + ci * 256 + c * 4);
            v += w4.x * s_p[half][p00 * 64 + ci] + w4.y * s_p[half][(p00 + 1) * 64 + ci]
               + w4.z * s_p[half][(p00 + 3) * 64 + ci] + w4.w * s_p[half][(p00 + 4) * 64 + ci];
        }
        s_q[half][pos * 64 + c] = fmaxf(v, 0.f);
    }
    __syncthreads();

    // conv3 2x2 -> (128,) + relu; thread st = output channel
    {
        float v = b3[st];
        #pragma unroll 8
        for (int ci = 0; ci < 64; ci++) {
            float4 w4 = *(const float4*)(g_w3T + ci * 512 + st * 4);
            v += w4.x * s_q[half][0 * 64 + ci] + w4.y * s_q[half][1 * 64 + ci]
               + w4.z * s_q[half][2 * 64 + ci] + w4.w * s_q[half][3 * 64 + ci];
        }
        g_x[b * 128 + st] = fmaxf(v, 0.f);
    }
}

// ---------------- K4: LSTM (8 elems/block, 128 threads, f32x2-packed) ---------
__global__ __launch_bounds__(128)
void k_lstm(const float* __restrict__ memory,
            const float* __restrict__ bih, const float* __restrict__ bhh,
            float* __restrict__ mem_out) {
    int j = threadIdx.x;
    int b0 = blockIdx.x * 8;
    __shared__ __align__(16) float s_x[8 * 128];
    __shared__ __align__(16) float s_h[8 * 128];
    for (int idx = j; idx < 8 * 128; idx += 128) {
        int bi = idx >> 7, k = idx & 127;
        s_x[idx] = g_x[(b0 + bi) * 128 + k];
        s_h[idx] = memory[(b0 + bi) * 256 + k];
    }
    unsigned long long a0[8], a1[8], a2[8], a3[8];
    float bb0 = bih[j]       + bhh[j];
    float bb1 = bih[128 + j] + bhh[128 + j];
    float bb2 = bih[256 + j] + bhh[256 + j];
    float bb3 = bih[384 + j] + bhh[384 + j];
    #pragma unroll
    for (int bi = 0; bi < 8; bi++) {
        a0[bi] = init2(bb0); a1[bi] = init2(bb1);
        a2[bi] = init2(bb2); a3[bi] = init2(bb3);
    }
    __syncthreads();

    for (int kc = 0; kc < 32; kc++) {
        {   // input-to-hidden
            ulonglong2 w0 = *(const ulonglong2*)(g_wihT + kc * 2048 + j * 4);
            ulonglong2 w1 = *(const ulonglong2*)(g_wihT + kc * 2048 + (128 + j) * 4);
            ulonglong2 w2 = *(const ulonglong2*)(g_wihT + kc * 2048 + (256 + j) * 4);
            ulonglong2 w3 = *(const ulonglong2*)(g_wihT + kc * 2048 + (384 + j) * 4);
            #pragma unroll
            for (int bi = 0; bi < 8; bi++) {
                ulonglong2 xv = *(const ulonglong2*)(s_x + bi * 128 + kc * 4);
                fma2(a0[bi], w0.x, xv.x); fma2(a0[bi], w0.y, xv.y);
                fma2(a1[bi], w1.x, xv.x); fma2(a1[bi], w1.y, xv.y);
                fma2(a2[bi], w2.x, xv.x); fma2(a2[bi], w2.y, xv.y);
                fma2(a3[bi], w3.x, xv.x); fma2(a3[bi], w3.y, xv.y);
            }
        }
        {   // hidden-to-hidden
            ulonglong2 w0 = *(const ulonglong2*)(g_whhT + kc * 2048 + j * 4);
            ulonglong2 w1 = *(const ulonglong2*)(g_whhT + kc * 2048 + (128 + j) * 4);
            ulonglong2 w2 = *(const ulonglong2*)(g_whhT + kc * 2048 + (256 + j) * 4);
            ulonglong2 w3 = *(const ulonglong2*)(g_whhT + kc * 2048 + (384 + j) * 4);
            #pragma unroll
            for (int bi = 0; bi < 8; bi++) {
                ulonglong2 hv = *(const ulonglong2*)(s_h + bi * 128 + kc * 4);
                fma2(a0[bi], w0.x, hv.x); fma2(a0[bi], w0.y, hv.y);
                fma2(a1[bi], w1.x, hv.x); fma2(a1[bi], w1.y, hv.y);
                fma2(a2[bi], w2.x, hv.x); fma2(a2[bi], w2.y, hv.y);
                fma2(a3[bi], w3.x, hv.x); fma2(a3[bi], w3.y, hv.y);
            }
        }
    }
    #pragma unroll
    for (int bi = 0; bi < 8; bi++) {
        float c_in = memory[(b0 + bi) * 256 + 128 + j];
        float cn = sigm_(hsum2(a1[bi])) * c_in + sigm_(hsum2(a0[bi])) * tanh_(hsum2(a2[bi]));
        float hn = sigm_(hsum2(a3[bi])) * tanh_(cn);
        mem_out[(b0 + bi) * 256 + j] = hn;
        mem_out[(b0 + bi) * 256 + 128 + j] = cn;
    }
}

// ---------------- K5: GRU over 20 steps (8 batch / block, f32x2-packed) -------
__global__ __launch_bounds__(128)
void k_gru(const int* __restrict__ text, const float* __restrict__ bhh) {
    int j = threadIdx.x;
    int b0 = blockIdx.x * 8;
    __shared__ __align__(16) float s_ht[8 * 128];
    __shared__ __align__(16) int s_w[8 * 20];
    for (int idx = j; idx < 160; idx += 128) s_w[idx] = text[b0 * 20 + idx];
    #pragma unroll
    for (int bi = 0; bi < 8; bi++) s_ht[bi * 128 + j] = 0.f;
    float htj[8];
    #pragma unroll
    for (int bi = 0; bi < 8; bi++) htj[bi] = 0.f;
    float bh_r = bhh[j], bh_z = bhh[128 + j], bh_n = bhh[256 + j];
    __syncthreads();

    for (int tt = 0; tt < 20; tt++) {
        unsigned long long ar[8], az[8], an[8];
        #pragma unroll
        for (int bi = 0; bi < 8; bi++) {
            ar[bi] = init2(bh_r); az[bi] = init2(bh_z); an[bi] = init2(bh_n);
        }
        for (int kc = 0; kc < 32; kc++) {
            ulonglong2 wr = *(const ulonglong2*)(g_gwhhT + kc * 1536 + j * 4);
            ulonglong2 wz = *(const ulonglong2*)(g_gwhhT + kc * 1536 + (128 + j) * 4);
            ulonglong2 wn = *(const ulonglong2*)(g_gwhhT + kc * 1536 + (256 + j) * 4);
            #pragma unroll
            for (int bi = 0; bi < 8; bi++) {
                ulonglong2 hv = *(const ulonglong2*)(s_ht + bi * 128 + kc * 4);
                fma2(ar[bi], wr.x, hv.x); fma2(ar[bi], wr.y, hv.y);
                fma2(az[bi], wz.x, hv.x); fma2(az[bi], wz.y, hv.y);
                fma2(an[bi], wn.x, hv.x); fma2(an[bi], wn.y, hv.y);
            }
        }
        __syncthreads();
        #pragma unroll
        for (int bi = 0; bi < 8; bi++) {
            const float* gi = g_GI + s_w[bi * 20 + tt] * 384;
            float r = sigm_(gi[j] + hsum2(ar[bi]));
            float z = sigm_(gi[128 + j] + hsum2(az[bi]));
            float n = tanh_(gi[256 + j] + r * hsum2(an[bi]));
            float h = (1.f - z) * n + z * htj[bi];
            htj[bi] = h;
            s_ht[bi * 128 + j] = h;
        }
        __syncthreads();
    }
    #pragma unroll
    for (int bi = 0; bi < 8; bi++) g_ht[(b0 + bi) * 128 + j] = htj[bi];
}

// ---------------- K6: actor/critic heads (16 batch / block, 256 threads) -----
__global__ __launch_bounds__(256)
void k_heads(const float* __restrict__ mem,
             const float* __restrict__ ab1, const float* __restrict__ aw2,
             const float* __restrict__ ab2, const float* __restrict__ cb1,
             const float* __restrict__ cw2, const float* __restrict__ cb2,
             float* __restrict__ lp, float* __restrict__ value) {
    int tid = threadIdx.x;
    int b0 = blockIdx.x * 16;
    __shared__ __align__(16) float s_emb[16 * 256];
    __shared__ __align__(16) float s_a1[16 * 256];
    __shared__ __align__(16) float s_logits[16 * 8];

    for (int idx = tid; idx < 16 * 128; idx += 256) {
        int bi = idx >> 7, k = idx & 127;
        s_emb[bi * 256 + k]       = mem[(b0 + bi) * 256 + k];
        s_emb[bi * 256 + 128 + k] = g_ht[(b0 + bi) * 128 + k];
    }
    __syncthreads();

    // actor layer 1 (packed)
    {
        unsigned long long acc[16];
        float bb = ab1[tid];
        #pragma unroll
        for (int bi = 0; bi < 16; bi++) acc[bi] = init2(bb);
        for (int kc = 0; kc < 64; kc++) {
            ulonglong2 w = *(const ulonglong2*)(g_aw1T + kc * 1024 + tid * 4);
            #pragma unroll
            for (int bi = 0; bi < 16; bi++) {
                ulonglong2 e = *(const ulonglong2*)(s_emb + bi * 256 + kc * 4);
                fma2(acc[bi], w.x, e.x); fma2(acc[bi], w.y, e.y);
            }
        }
        #pragma unroll
        for (int bi = 0; bi < 16; bi++) s_a1[bi * 256 + tid] = tanh_(hsum2(acc[bi]));
    }
    __syncthreads();

    int warp = tid >> 5, lane = tid & 31;
    for (int bi = warp * 2; bi < warp * 2 + 2; bi++) {
        for (int a = 0; a < 7; a++) {
            float s = 0.f;
            for (int k = lane; k < 256; k += 32) s += aw2[a * 256 + k] * s_a1[bi * 256 + k];
            #pragma unroll
            for (int off = 16; off; off >>= 1) s += __shfl_xor_sync(0xffffffffu, s, off);
            if (lane == 0) s_logits[bi * 8 + a] = s + ab2[a];
        }
    }
    __syncthreads();

    // critic layer 1 (packed; reuses s_a1)
    {
        unsigned long long acc[16];
        float bb = cb1[tid];
        #pragma unroll
        for (int bi = 0; bi < 16; bi++) acc[bi] = init2(bb);
        for (int kc = 0; kc < 64; kc++) {
            ulonglong2 w = *(const ulonglong2*)(g_cw1T + kc * 1024 + tid * 4);
            #pragma unroll
            for (int bi = 0; bi < 16; bi++) {
                ulonglong2 e = *(const ulonglong2*)(s_emb + bi * 256 + kc * 4);
                fma2(acc[bi], w.x, e.x); fma2(acc[bi], w.y, e.y);
            }
        }
        #pragma unroll
        for (int bi = 0; bi < 16; bi++) s_a1[bi * 256 + tid] = tanh_(hsum2(acc[bi]));
    }
    if (tid < 16) {
        float m = -1e30f;
        #pragma unroll
        for (int a = 0; a < 7; a++) m = fmaxf(m, s_logits[tid * 8 + a]);
        float sum = 0.f;
        #pragma unroll
        for (int a = 0; a < 7; a++) sum += expf(s_logits[tid * 8 + a] - m);
        float lse = m + logf(sum);
        #pragma unroll
        for (int a = 0; a < 7; a++) lp[(b0 + tid) * 7 + a] = s_logits[tid * 8 + a] - lse;
    }
    __syncthreads();

    for (int bi = warp * 2; bi < warp * 2 + 2; bi++) {
        float s = 0.f;
        for (int k = lane; k < 256; k += 32) s += cw2[k] * s_a1[bi * 256 + k];
        #pragma unroll
        for (int off = 16; off; off >>= 1) s += __shfl_xor_sync(0xffffffffu, s, off);
        if (lane == 0) value[b0 + bi] = s + cb2[0];
    }
}

// ---------------- launch ----------------
extern "C" void kernel_launch(void* const* d_in, const int* in_sizes, int n_in,
                              void* d_out, int out_size) {
    const int*   image  = (const int*)  d_in[0];
    const float* memory = (const float*)d_in[1];
    const int*   text   = (const int*)  d_in[2];
    const float* obj_e  = (const float*)d_in[3];
    const float* col_e  = (const float*)d_in[4];
    const float* st_e   = (const float*)d_in[5];
    const float* c1w    = (const float*)d_in[6];
    const float* c1b    = (const float*)d_in[7];
    const float* c2w    = (const float*)d_in[8];
    const float* c2b    = (const float*)d_in[9];
    const float* c3w    = (const float*)d_in[10];
    const float* c3b    = (const float*)d_in[11];
    const float* lwih   = (const float*)d_in[12];
    const float* lwhh   = (const float*)d_in[13];
    const float* lbih   = (const float*)d_in[14];
    const float* lbhh   = (const float*)d_in[15];
    const float* wemb   = (const float*)d_in[16];
    const float* gwih   = (const float*)d_in[17];
    const float* gwhh   = (const float*)d_in[18];
    const float* gbih   = (const float*)d_in[19];
    const float* gbhh   = (const float*)d_in[20];
    const float* aw1    = (const float*)d_in[21];
    const float* ab1    = (const float*)d_in[22];
    const float* aw2    = (const float*)d_in[23];
    const float* ab2    = (const float*)d_in[24];
    const float* cw1    = (const float*)d_in[25];
    const float* cb1    = (const float*)d_in[26];
    const float* cw2    = (const float*)d_in[27];
    const float* cb2    = (const float*)d_in[28];

    const int B = in_sizes[1] / 256;   // 8192
    float* out   = (float*)d_out;
    float* lp    = out;                 // (B,7)
    float* value = out + (size_t)B * 7; // (B,)
    float* memo  = out + (size_t)B * 8; // (B,256)

    dim3 pgrid(64, 7);
    k_prep<<<pgrid, 256>>>(lwih, lwhh, gwhh, aw1, cw1, c2w, c3w);
    k_build_t1<<<4 * 132, 64>>>(obj_e, col_e, st_e, c1w);
    k_build_gi<<<100, 384>>>(wemb, gwih, gbih);

    k_conv<<<B / 2, 256>>>(image, c1b, c2b, c3b);
    k_lstm<<<B / 8, 128>>>(memory, lbih, lbhh, memo);
    k_gru<<<B / 8, 128>>>(text, gbhh);
    k_heads<<<B / 16, 256>>>(memo, ab1, aw2, ab2, cb1, cw2, cb2, lp, value);
}